// round 3
// baseline (speedup 1.0000x reference)
#include <cuda_runtime.h>
#include <cstdint>

// ---------------------------------------------------------------------------
// DeformRoIPooling (deformable PS-RoI pooling), GROUP_SIZE=1 specialization.
//
// data:   (B=2, C=256, H=128, W=128) f32
// rois:   (N=128, 5) f32  [b, x1, y1, x2, y2]
// offset: (N=128, 2, 7, 7) f32
// out:    (N=128, 256, 7, 7) f32
//
// R3: separable per-pixel weight dedup — the 16 (4x4) samples of a bin are
//     collapsed into a rank-1 weight grid WY(py)*WX(px) over the distinct
//     pixel rows/cols they touch (~3x3 typical), cutting gather loads ~6x.
// ---------------------------------------------------------------------------

#define BQ   2
#define CQ   256
#define HQ   128
#define WQ   128
#define NROI 128
#define PQ   7
#define SQ   4
#define SPATIAL_SCALE 0.0625f
#define TRANS_STD 0.1f

// 32 MB transposed scratch: (B, H, W, C) — L2-resident (126MB L2)
__device__ float g_tdata[(size_t)BQ * HQ * WQ * CQ];

// ---------------------------------------------------------------------------
// Vectorized transpose: per batch, (C=256) x (P=16384) -> (P) x (C).
// ---------------------------------------------------------------------------
__global__ void __launch_bounds__(256) transpose_kernel(const float* __restrict__ src) {
    __shared__ float tile[32][68];
    const int b  = blockIdx.z;
    const int c0 = blockIdx.y * 32;
    const int p0 = blockIdx.x * 64;
    const float* s = src + ((size_t)b * CQ + c0) * (HQ * WQ) + p0;
    float* d       = g_tdata + (size_t)b * HQ * WQ * CQ;

    const int i = threadIdx.x;
    {
        const int c = i >> 4;
        const int q = i & 15;
        #pragma unroll
        for (int r = 0; r < 2; r++) {
            float4 v = *(const float4*)(s + (size_t)(c + 16 * r) * (HQ * WQ) + 4 * q);
            *(float4*)&tile[c + 16 * r][4 * q] = v;
        }
    }
    __syncthreads();
    {
        const int p   = i >> 2;
        const int cq0 = i & 3;
        #pragma unroll
        for (int r = 0; r < 2; r++) {
            const int cq = cq0 + 4 * r;
            float4 v;
            v.x = tile[4 * cq + 0][p];
            v.y = tile[4 * cq + 1][p];
            v.z = tile[4 * cq + 2][p];
            v.w = tile[4 * cq + 3][p];
            *(float4*)(d + (size_t)(p0 + p) * CQ + c0 + 4 * cq) = v;
        }
    }
}

// ---------------------------------------------------------------------------
// Packed f32x2 helpers (Blackwell FFMA2 via PTX)
// ---------------------------------------------------------------------------
__device__ __forceinline__ unsigned long long pack2(float v) {
    unsigned long long r;
    asm("mov.b64 %0, {%1, %1};" : "=l"(r) : "f"(v));
    return r;
}
__device__ __forceinline__ void fma2(unsigned long long& d,
                                     unsigned long long a,
                                     unsigned long long b) {
    asm("fma.rn.f32x2 %0, %1, %2, %0;" : "+l"(d) : "l"(a), "l"(b));
}
__device__ __forceinline__ void unpack2(unsigned long long v, float& lo, float& hi) {
    asm("mov.b64 {%0, %1}, %2;" : "=f"(lo), "=f"(hi) : "l"(v));
}

// ---------------------------------------------------------------------------
// Pool: block = 256 threads = 4 bins x 64 threads; thread t -> channels 4t..4t+3.
// Warps never span bins -> all control flow is warp-uniform.
// ---------------------------------------------------------------------------
__global__ void __launch_bounds__(256, 4) pool_kernel(
    const float* __restrict__ rois,
    const float* __restrict__ offset,
    float* __restrict__ out)
{
    const int bin = blockIdx.x * 4 + threadIdx.y;  // 0..51
    if (bin >= PQ * PQ) return;
    const int n   = blockIdx.y;                    // 0..127
    const int ph  = bin / PQ;
    const int pw  = bin - ph * PQ;
    const int t   = threadIdx.x;                   // 0..63

    // --- geometry (replicates reference IEEE f32 ops) ---
    const float* r = rois + n * 5;
    const int   b  = (int)__ldg(&r[0]);
    const float rsw = rintf(__ldg(&r[1])) * SPATIAL_SCALE - 0.5f;
    const float rsh = rintf(__ldg(&r[2])) * SPATIAL_SCALE - 0.5f;
    const float rew = (rintf(__ldg(&r[3])) + 1.0f) * SPATIAL_SCALE - 0.5f;
    const float reh = (rintf(__ldg(&r[4])) + 1.0f) * SPATIAL_SCALE - 0.5f;
    const float rw = fmaxf(rew - rsw, 0.1f);
    const float rh = fmaxf(reh - rsh, 0.1f);
    const float binw = rw / (float)PQ;
    const float binh = rh / (float)PQ;
    const float subw = binw / (float)SQ;
    const float subh = binh / (float)SQ;

    const int part_h = (int)floorf((float)ph / (float)PQ * (float)PQ);
    const int part_w = (int)floorf((float)pw / (float)PQ * (float)PQ);

    const float tx_off = __ldg(&offset[n * (2 * PQ * PQ) + part_h * PQ + part_w]) * TRANS_STD;
    const float ty_off = __ldg(&offset[n * (2 * PQ * PQ) + PQ * PQ + part_h * PQ + part_w]) * TRANS_STD;

    const float wstart = (float)pw * binw + rsw + tx_off * rw;
    const float hstart = (float)ph * binh + rsh + ty_off * rh;

    // --- per-sample separable weights ---
    // Each sample ih contributes (1-dy) to row y0 and dy to row y0+1
    // (when dy==0 the second weight is 0, so treating y1 as y0+1 is exact).
    float a0y[SQ], a1y[SQ];  int y0i[SQ];
    float a0x[SQ], a1x[SQ];  int x0i[SQ];
    float nvh = 0.f, nvw = 0.f;
    int ylast = 0, xlast = 0;

    #pragma unroll
    for (int ih = 0; ih < SQ; ih++) {
        const float h  = hstart + (float)ih * subh;
        const bool  vh = (h >= -0.5f) && (h <= (float)HQ - 0.5f);
        nvh += vh ? 1.f : 0.f;
        const float hc  = fminf(fmaxf(h, 0.f), (float)(HQ - 1));
        const float y0f = floorf(hc);
        const float dy  = hc - y0f;
        y0i[ih] = (int)y0f;
        a0y[ih] = vh ? (1.f - dy) : 0.f;
        a1y[ih] = vh ? dy : 0.f;
        if (ih == SQ - 1) ylast = (int)ceilf(hc);
    }
    #pragma unroll
    for (int iw = 0; iw < SQ; iw++) {
        const float w  = wstart + (float)iw * subw;
        const bool  vw = (w >= -0.5f) && (w <= (float)WQ - 0.5f);
        nvw += vw ? 1.f : 0.f;
        const float wc  = fminf(fmaxf(w, 0.f), (float)(WQ - 1));
        const float x0f = floorf(wc);
        const float dx  = wc - x0f;
        x0i[iw] = (int)x0f;
        a0x[iw] = vw ? (1.f - dx) : 0.f;
        a1x[iw] = vw ? dx : 0.f;
        if (iw == SQ - 1) xlast = (int)ceilf(wc);
    }

    const float count = nvh * nvw;
    unsigned long long acc01 = 0ull, acc23 = 0ull;

    if (count > 0.f) {
        const float* base = g_tdata + (size_t)b * HQ * WQ * CQ;
        const int ybase = y0i[0];
        const int xbase = x0i[0];

        for (int yy = ybase; yy <= ylast; ++yy) {          // <= ~7 iters, uniform
            float wy = 0.f;
            #pragma unroll
            for (int ih = 0; ih < SQ; ih++) {
                wy += (y0i[ih] == yy)     ? a0y[ih] : 0.f;
                wy += (y0i[ih] == yy - 1) ? a1y[ih] : 0.f;
            }
            if (wy == 0.f) continue;                       // uniform skip
            const float* rowp = base + (size_t)yy * (WQ * CQ);

            for (int xx = xbase; xx <= xlast; ++xx) {      // <= ~7 iters, uniform
                float wx = 0.f;
                #pragma unroll
                for (int iw = 0; iw < SQ; iw++) {
                    wx += (x0i[iw] == xx)     ? a0x[iw] : 0.f;
                    wx += (x0i[iw] == xx - 1) ? a1x[iw] : 0.f;
                }
                if (wx == 0.f) continue;                   // uniform skip

                const unsigned long long wgt = pack2(wy * wx);
                const ulonglong2 v = __ldg((const ulonglong2*)(rowp + (size_t)xx * CQ) + t);
                fma2(acc01, wgt, v.x);
                fma2(acc23, wgt, v.y);
            }
        }
    }

    float a0, a1, a2, a3;
    unpack2(acc01, a0, a1);
    unpack2(acc23, a2, a3);

    float r0 = 0.f, r1 = 0.f, r2 = 0.f, r3 = 0.f;
    if (count > 0.f) {
        r0 = a0 / count; r1 = a1 / count; r2 = a2 / count; r3 = a3 / count;
    }

    // out layout (N, C, 7, 7): channel stride = 49
    float* o = out + ((size_t)n * CQ + 4 * t) * (PQ * PQ) + ph * PQ + pw;
    o[0]            = r0;
    o[PQ * PQ]      = r1;
    o[2 * PQ * PQ]  = r2;
    o[3 * PQ * PQ]  = r3;
}

extern "C" void kernel_launch(void* const* d_in, const int* in_sizes, int n_in,
                              void* d_out, int out_size) {
    const float* data   = (const float*)d_in[0];
    const float* rois   = (const float*)d_in[1];
    const float* offset = (const float*)d_in[2];
    float* out = (float*)d_out;

    dim3 tg(HQ * WQ / 64, CQ / 32, BQ);     // (256, 8, 2)
    transpose_kernel<<<tg, 256>>>(data);

    dim3 pg((PQ * PQ + 3) / 4, NROI);       // (13, 128)
    dim3 pb(64, 4);
    pool_kernel<<<pg, pb>>>(rois, offset, out);
}